// round 2
// baseline (speedup 1.0000x reference)
#include <cuda_runtime.h>
#include <math.h>

#define BATCH 8
#define NPROP 1000
#define NCLS  80
#define NLOG  81
#define DFEAT 2048
#define KCAND 1024
#define NFLAT (NPROP*NCLS)   /* 80000 */
#define CHUNK 79             /* ceil(80000/1024) */
#define NTH   10
#define SCORE_T 1e-4f

/* ---------------- scratch (static device globals; no allocation) -------- */
__device__ float g_scores[BATCH][NFLAT];
__device__ float g_box  [BATCH][KCAND][4];
__device__ float g_area [BATCH][KCAND];
__device__ float g_val  [BATCH][KCAND];
__device__ int   g_prop [BATCH][KCAND];
__device__ unsigned long long g_sup[BATCH][KCAND][KCAND/8]; /* [j][i] bytes: #thresh suppressed */
__device__ int   g_sel  [BATCH][6];

/* ---------------- kernel 1: softmax probs -> scores --------------------- */
__global__ void k_softmax(const float* __restrict__ logits)
{
    int gw   = blockIdx.x * (blockDim.x >> 5) + (threadIdx.x >> 5);
    int lane = threadIdx.x & 31;
    if (gw >= BATCH * NPROP) return;
    int b = gw / NPROP, r = gw % NPROP;
    const float* p = logits + (size_t)(b * NPROP + r) * NLOG;

    float v0 = p[lane];
    float v1 = p[lane + 32];
    float v2 = (lane + 64 < NLOG) ? p[lane + 64] : -INFINITY;
    float m = fmaxf(fmaxf(v0, v1), v2);
    #pragma unroll
    for (int o = 16; o; o >>= 1) m = fmaxf(m, __shfl_xor_sync(0xffffffffu, m, o));
    float e0 = expf(v0 - m);
    float e1 = expf(v1 - m);
    float e2 = (lane + 64 < NLOG) ? expf(v2 - m) : 0.0f;
    float s = e0 + e1 + e2;
    #pragma unroll
    for (int o = 16; o; o >>= 1) s += __shfl_xor_sync(0xffffffffu, s, o);

    float* out = &g_scores[b][r * NCLS];
    out[lane]      = e0 / s;
    out[lane + 32] = e1 / s;
    if (lane + 64 < NCLS) out[lane + 64] = e2 / s;
}

/* ---------------- block exclusive scan (1024 threads) -------------------- */
__device__ __forceinline__ int blk_excl_scan(int v, int tid, int* wtmp)
{
    int lane = tid & 31, wid = tid >> 5;
    int inc = v;
    #pragma unroll
    for (int o = 1; o < 32; o <<= 1) {
        int u = __shfl_up_sync(0xffffffffu, inc, o);
        if (lane >= o) inc += u;
    }
    if (lane == 31) wtmp[wid] = inc;
    __syncthreads();
    if (wid == 0) {
        int x = wtmp[lane];
        int i2 = x;
        #pragma unroll
        for (int o = 1; o < 32; o <<= 1) {
            int u = __shfl_up_sync(0xffffffffu, i2, o);
            if (lane >= o) i2 += u;
        }
        wtmp[lane] = i2 - x;   /* exclusive warp offsets */
    }
    __syncthreads();
    int res = wtmp[wid] + inc - v;
    __syncthreads();
    return res;
}

/* ---------------- kernel 2: exact top-1024 + sort + box prep ------------ */
__global__ void __launch_bounds__(1024) k_select(const float* __restrict__ boxes,
                                                 const int*   __restrict__ hw)
{
    int b = blockIdx.x;
    int tid = threadIdx.x, lane = tid & 31, wid = tid >> 5;

    __shared__ int hist[2048];
    __shared__ unsigned long long sm64[KCAND];
    __shared__ int wtmp[32];
    __shared__ int sh_digit, sh_need;

    const float* sc = g_scores[b];

    unsigned prefix = 0;
    int need = KCAND;

    const int shifts[3] = {21, 10, 0};
    const int nbits [3] = {11, 11, 10};

    for (int p = 0; p < 3; ++p) {
        int NB = 1 << nbits[p];
        int sh = shifts[p];
        for (int i = tid; i < NB; i += 1024) hist[i] = 0;
        __syncthreads();

        for (int k = 0; k < CHUNK; ++k) {
            int e = tid * CHUNK + k;
            if (e < NFLAT) {
                float s = sc[e];
                unsigned key = (s > SCORE_T) ? __float_as_uint(s) : 0u;
                bool ok = (p == 0) || ((key >> (sh + nbits[p])) == prefix);
                if (ok) {
                    int d = (key >> sh) & (NB - 1);
                    unsigned pm = __match_any_sync(__activemask(), d);
                    if ((int)(__ffs(pm) - 1) == lane)
                        atomicAdd(&hist[d], __popc(pm));
                }
            }
        }
        __syncthreads();

        if (wid == 0) {
            int run = 0, done = 0;
            for (int g = 0; g < NB / 32 && !done; ++g) {
                int bin = NB - 1 - (g * 32 + lane);   /* lane0 = highest bin */
                int c = hist[bin];
                int inc = c;
                #pragma unroll
                for (int o = 1; o < 32; o <<= 1) {
                    int u = __shfl_up_sync(0xffffffffu, inc, o);
                    if (lane >= o) inc += u;
                }
                int cum = run + inc;
                unsigned bal = __ballot_sync(0xffffffffu, cum >= need);
                if (bal) {
                    int fl = __ffs(bal) - 1;
                    if (lane == fl) {
                        sh_digit = bin;
                        sh_need  = need - (cum - c);  /* slots left inside this digit */
                    }
                    done = 1;
                }
                run += __shfl_sync(0xffffffffu, inc, 31);
            }
        }
        __syncthreads();
        prefix = (prefix << nbits[p]) | (unsigned)sh_digit;
        need = sh_need;
        __syncthreads();
    }

    unsigned pivot = prefix;
    int G = KCAND - need;   /* count strictly greater than pivot */

    /* count per-thread greater/equal over contiguous index range */
    int cg = 0, ce = 0;
    for (int k = 0; k < CHUNK; ++k) {
        int e = tid * CHUNK + k;
        if (e < NFLAT) {
            float s = sc[e];
            unsigned key = (s > SCORE_T) ? __float_as_uint(s) : 0u;
            cg += (key > pivot);
            ce += (key == pivot);
        }
    }
    int goff = blk_excl_scan(cg, tid, wtmp);
    int eoff = blk_excl_scan(ce, tid, wtmp);

    int wg = goff, we = eoff;
    for (int k = 0; k < CHUNK; ++k) {
        int e = tid * CHUNK + k;
        if (e < NFLAT) {
            float s = sc[e];
            unsigned key = (s > SCORE_T) ? __float_as_uint(s) : 0u;
            if (key > pivot) {
                sm64[wg++] = ((unsigned long long)(key ^ 0xFFFFFFFFu) << 32) | (unsigned)e;
            } else if (key == pivot) {
                int pos = G + we;
                we++;
                if (pos < KCAND)
                    sm64[pos] = ((unsigned long long)(key ^ 0xFFFFFFFFu) << 32) | (unsigned)e;
            }
        }
    }
    __syncthreads();

    /* bitonic sort ascending on (~val, idx) => val desc, idx asc on ties */
    for (int k2 = 2; k2 <= KCAND; k2 <<= 1) {
        for (int j = k2 >> 1; j > 0; j >>= 1) {
            int ixj = tid ^ j;
            if (ixj > tid) {
                unsigned long long a = sm64[tid], c = sm64[ixj];
                bool up = ((tid & k2) == 0);
                if ((a > c) == up) { sm64[tid] = c; sm64[ixj] = a; }
            }
            __syncthreads();
        }
    }

    /* finalize candidate r = tid */
    unsigned long long v = sm64[tid];
    unsigned key = (unsigned)(v >> 32) ^ 0xFFFFFFFFu;
    int idx = (int)(v & 0xFFFFFFFFu);
    float val = __uint_as_float(key);
    int cls  = idx % NCLS;
    int prop = idx / NCLS;

    float h = (float)hw[b * 2 + 0];
    float w = (float)hw[b * 2 + 1];
    const float* bp = boxes + ((size_t)(b * NPROP + prop) * NCLS + cls) * 4;
    float x1 = fminf(fmaxf(bp[0], 0.0f), w);
    float y1 = fminf(fmaxf(bp[1], 0.0f), h);
    float x2 = fminf(fmaxf(bp[2], 0.0f), w);
    float y2 = fminf(fmaxf(bp[3], 0.0f), h);
    float off = (float)cls * 4096.0f;
    x1 += off; y1 += off; x2 += off; y2 += off;

    g_box[b][tid][0] = x1; g_box[b][tid][1] = y1;
    g_box[b][tid][2] = x2; g_box[b][tid][3] = y2;
    g_area[b][tid] = (x2 - x1) * (y2 - y1);
    g_val[b][tid]  = val;
    g_prop[b][tid] = prop;
}

/* ---------------- kernel 3: per-pair threshold counts -------------------- */
__global__ void k_iou()
{
    int j = blockIdx.x & (KCAND - 1);
    int b = blockIdx.x >> 10;
    int tid = threadIdx.x;   /* 128 threads; each handles 8 i's */

    const float4* gb = (const float4*)g_box[b];
    float4 bj = gb[j];
    float aj = g_area[b][j];

    unsigned long long w = 0;
    int i0 = tid * 8;
    #pragma unroll
    for (int q = 0; q < 8; ++q) {
        int i = i0 + q;
        float4 bi = gb[i];
        float iw = fminf(bj.z, bi.z) - fmaxf(bj.x, bi.x);
        float ih = fminf(bj.w, bi.w) - fmaxf(bj.y, bi.y);
        iw = fmaxf(iw, 0.0f);
        ih = fmaxf(ih, 0.0f);
        float inter = iw * ih;
        float uni = aj + g_area[b][i] - inter;
        float iou = (uni > 0.0f) ? (inter / uni) : 0.0f;
        int c = 0;
        c += (iou > 0.001f); c += (iou > 0.101f); c += (iou > 0.201f);
        c += (iou > 0.301f); c += (iou > 0.401f); c += (iou > 0.501f);
        c += (iou > 0.601f); c += (iou > 0.701f); c += (iou > 0.801f);
        c += (iou > 0.901f);
        w |= ((unsigned long long)(unsigned)c) << (8 * q);
    }
    g_sup[b][j][tid] = w;
}

/* ---------------- kernel 4: bit-parallel tiled greedy NMS + select ------- */
__global__ void __launch_bounds__(1024) k_nms()
{
    int b = blockIdx.x;
    int tid = threadIdx.x, lane = tid & 31, wid = tid >> 5;

    __shared__ int keep_sh[KCAND];
    __shared__ int counts[NTH];
    __shared__ int wtmp[32];
    __shared__ int sh_tsel;

    float val = g_val[b][tid];
    int kreg = (val > SCORE_T) ? 0x3FF : 0;
    if (tid < NTH) counts[tid] = 0;

    for (int ti = 0; ti < 32; ++ti) {
        if (wid == ti) {
            /* intra-tile serial suppression via warp shuffles */
            const unsigned long long* sp = &g_sup[b][tid][ti * 4];
            unsigned long long s0 = sp[0], s1 = sp[1], s2 = sp[2], s3 = sp[3];
            unsigned long long ss[4] = {s0, s1, s2, s3};
            #pragma unroll
            for (int l = 0; l < 32; ++l) {
                int m = __shfl_sync(0xffffffffu, kreg, l);
                if (lane > l) {
                    int c = (int)((ss[l >> 3] >> ((l & 7) * 8)) & 0xFF);
                    kreg &= ~(m & ((1 << c) - 1));
                }
            }
            keep_sh[tid] = kreg;
        }
        __syncthreads();
        if (tid >= (ti + 1) * 32) {
            /* cross-tile parallel suppression */
            const unsigned long long* sp = &g_sup[b][tid][ti * 4];
            unsigned long long s0 = sp[0], s1 = sp[1], s2 = sp[2], s3 = sp[3];
            unsigned long long ss[4] = {s0, s1, s2, s3};
            int acc = 0;
            #pragma unroll
            for (int l = 0; l < 32; ++l) {
                int c = (int)((ss[l >> 3] >> ((l & 7) * 8)) & 0xFF);
                acc |= keep_sh[ti * 32 + l] & ((1 << c) - 1);
            }
            kreg &= ~acc;
        }
    }
    __syncthreads();

    /* per-threshold counts */
    #pragma unroll
    for (int t = 0; t < NTH; ++t) {
        unsigned bal = __ballot_sync(0xffffffffu, (kreg >> t) & 1);
        if (lane == 0) atomicAdd(&counts[t], __popc(bal));
    }
    __syncthreads();
    if (tid == 0) {
        int t = NTH - 1;
        for (int q = 0; q < NTH; ++q)
            if (counts[q] >= 6) { t = q; break; }
        sh_tsel = t;
    }
    __syncthreads();

    int tsel = sh_tsel;
    int ktot = counts[tsel];
    int ksel = (kreg >> tsel) & 1;

    int rank = blk_excl_scan(ksel, tid, wtmp);
    if (ksel && rank < 6) g_sel[b][rank] = g_prop[b][tid];

    if (ktot < 6) {  /* pathological fallback: pad with lowest-index non-kept (ties at -inf) */
        int r2 = blk_excl_scan(1 - ksel, tid, wtmp);
        if (!ksel && (ktot + r2) < 6) g_sel[b][ktot + r2] = g_prop[b][tid];
    }
}

/* ---------------- kernel 5: feature gather (B, D, 6) --------------------- */
__global__ void k_gather(const float* __restrict__ feats, float* __restrict__ out)
{
    int g = blockIdx.x * blockDim.x + threadIdx.x;
    if (g >= BATCH * DFEAT * 6) return;
    int b = g / (DFEAT * 6);
    int r = g % (DFEAT * 6);
    int d = r / 6;
    int j = r % 6;
    int p = g_sel[b][j];
    out[g] = feats[((size_t)b * NPROP + p) * DFEAT + d];
}

/* ---------------- launch -------------------------------------------------- */
extern "C" void kernel_launch(void* const* d_in, const int* in_sizes, int n_in,
                              void* d_out, int out_size)
{
    (void)in_sizes; (void)n_in; (void)out_size;
    const float* logits = (const float*)d_in[0];
    const float* boxes  = (const float*)d_in[1];
    const float* feats  = (const float*)d_in[2];
    const int*   hw     = (const int*)  d_in[3];
    float* out = (float*)d_out;

    k_softmax<<<(BATCH * NPROP + 3) / 4, 128>>>(logits);
    k_select<<<BATCH, 1024>>>(boxes, hw);
    k_iou<<<BATCH * KCAND, 128>>>();
    k_nms<<<BATCH, 1024>>>();
    k_gather<<<(BATCH * DFEAT * 6 + 255) / 256, 256>>>(feats, out);
}

// round 4
// speedup vs baseline: 1.5009x; 1.5009x over previous
#include <cuda_runtime.h>
#include <math.h>

#define BATCH 8
#define NPROP 1000
#define NCLS  80
#define NLOG  81
#define DFEAT 2048
#define KCAND 1024
#define NFLAT (NPROP*NCLS)   /* 80000 */
#define CHUNK 79             /* ceil(80000/1024) */
#define NTH   10
#define SCORE_T 1e-4f

/* ---------------- scratch (static device globals; no allocation) -------- */
__device__ float g_scores[BATCH][NFLAT];
__device__ float g_box  [BATCH][KCAND][4];
__device__ float g_area [BATCH][KCAND];
__device__ float g_val  [BATCH][KCAND];
__device__ int   g_prop [BATCH][KCAND];
__device__ int   g_member[BATCH][KCAND];    /* candidates grouped by class, idx asc in group */
__device__ int   g_cstart[BATCH][NCLS + 1]; /* group offsets */
__device__ int   g_coff  [BATCH][NCLS + 1]; /* prefix of n_c^2 into g_cmat */
__device__ int   g_cnt   [BATCH][NCLS];
__device__ unsigned char g_cmat[BATCH][1 << 20]; /* per-class pair threshold counts */

/* ---------------- kernel 1: softmax probs -> scores --------------------- */
__global__ void k_softmax(const float* __restrict__ logits)
{
    int gw   = blockIdx.x * (blockDim.x >> 5) + (threadIdx.x >> 5);
    int lane = threadIdx.x & 31;
    if (gw >= BATCH * NPROP) return;
    int b = gw / NPROP, r = gw % NPROP;
    const float* p = logits + (size_t)(b * NPROP + r) * NLOG;

    float v0 = p[lane];
    float v1 = p[lane + 32];
    float v2 = (lane + 64 < NLOG) ? p[lane + 64] : -INFINITY;
    float m = fmaxf(fmaxf(v0, v1), v2);
    #pragma unroll
    for (int o = 16; o; o >>= 1) m = fmaxf(m, __shfl_xor_sync(0xffffffffu, m, o));
    float e0 = expf(v0 - m);
    float e1 = expf(v1 - m);
    float e2 = (lane + 64 < NLOG) ? expf(v2 - m) : 0.0f;
    float s = e0 + e1 + e2;
    #pragma unroll
    for (int o = 16; o; o >>= 1) s += __shfl_xor_sync(0xffffffffu, s, o);

    float* out = &g_scores[b][r * NCLS];
    out[lane]      = e0 / s;
    out[lane + 32] = e1 / s;
    if (lane + 64 < NCLS) out[lane + 64] = e2 / s;
}

/* ---------------- block exclusive scan (1024 threads) -------------------- */
__device__ __forceinline__ int blk_excl_scan(int v, int tid, int* wtmp)
{
    int lane = tid & 31, wid = tid >> 5;
    int inc = v;
    #pragma unroll
    for (int o = 1; o < 32; o <<= 1) {
        int u = __shfl_up_sync(0xffffffffu, inc, o);
        if (lane >= o) inc += u;
    }
    if (lane == 31) wtmp[wid] = inc;
    __syncthreads();
    if (wid == 0) {
        int x = wtmp[lane];
        int i2 = x;
        #pragma unroll
        for (int o = 1; o < 32; o <<= 1) {
            int u = __shfl_up_sync(0xffffffffu, i2, o);
            if (lane >= o) i2 += u;
        }
        wtmp[lane] = i2 - x;   /* exclusive warp offsets */
    }
    __syncthreads();
    int res = wtmp[wid] + inc - v;
    __syncthreads();
    return res;
}

/* ---------------- kernel 2: exact top-1024 + sort + box prep + class lists */
__global__ void __launch_bounds__(1024) k_select(const float* __restrict__ boxes,
                                                 const int*   __restrict__ hw)
{
    int b = blockIdx.x;
    int tid = threadIdx.x, lane = tid & 31, wid = tid >> 5;

    __shared__ int hist[2048];
    __shared__ unsigned long long sm64[KCAND];
    __shared__ int wtmp[32];
    __shared__ int sh_digit, sh_need, sh_E;
    __shared__ unsigned short h2[NCLS][32];
    __shared__ int sh_cnt[NCLS];
    __shared__ int sh_cstart[NCLS + 1];
    __shared__ int sh_coff[NCLS + 1];

    const float* sc = g_scores[b];

    unsigned prefix = 0;
    int need = KCAND;

    const int shifts[3] = {21, 10, 0};
    const int nbits [3] = {11, 11, 10};

    for (int p = 0; p < 3; ++p) {
        int NB = 1 << nbits[p];
        int sh = shifts[p];
        for (int i = tid; i < NB; i += 1024) hist[i] = 0;
        __syncthreads();

        /* coalesced strided read */
        for (int k = 0; k < CHUNK; ++k) {
            int e = tid + (k << 10);
            if (e < NFLAT) {
                float s = sc[e];
                unsigned key = (s > SCORE_T) ? __float_as_uint(s) : 0u;
                bool ok = (p == 0) || ((key >> (sh + nbits[p])) == prefix);
                if (ok) {
                    int d = (key >> sh) & (NB - 1);
                    unsigned pm = __match_any_sync(__activemask(), d);
                    if ((int)(__ffs(pm) - 1) == lane)
                        atomicAdd(&hist[d], __popc(pm));
                }
            }
        }
        __syncthreads();

        if (wid == 0) {
            int run = 0, done = 0;
            for (int g = 0; g < NB / 32 && !done; ++g) {
                int bin = NB - 1 - (g * 32 + lane);   /* lane0 = highest bin */
                int c = hist[bin];
                int inc = c;
                #pragma unroll
                for (int o = 1; o < 32; o <<= 1) {
                    int u = __shfl_up_sync(0xffffffffu, inc, o);
                    if (lane >= o) inc += u;
                }
                int cum = run + inc;
                unsigned bal = __ballot_sync(0xffffffffu, cum >= need);
                if (bal) {
                    int fl = __ffs(bal) - 1;
                    if (lane == fl) {
                        sh_digit = bin;
                        sh_need  = need - (cum - c);  /* slots left inside this digit */
                    }
                    done = 1;
                }
                run += __shfl_sync(0xffffffffu, inc, 31);
            }
        }
        __syncthreads();
        prefix = (prefix << nbits[p]) | (unsigned)sh_digit;
        need = sh_need;
        __syncthreads();
    }

    unsigned pivot = prefix;
    int G = KCAND - need;   /* count strictly greater than pivot */

    /* count pass (coalesced) */
    int cg = 0, ce = 0;
    for (int k = 0; k < CHUNK; ++k) {
        int e = tid + (k << 10);
        if (e < NFLAT) {
            float s = sc[e];
            unsigned key = (s > SCORE_T) ? __float_as_uint(s) : 0u;
            cg += (key > pivot);
            ce += (key == pivot);
        }
    }
    int goff = blk_excl_scan(cg, tid, wtmp);
    int eoff = blk_excl_scan(ce, tid, wtmp);
    if (tid == 1023) sh_E = eoff + ce;
    __syncthreads();
    int E_total = sh_E;
    bool fastpath = (E_total == need);

    /* compact pass (coalesced); ordering repaired by the bitonic sort below */
    {
        int wg = goff, we = eoff;
        for (int k = 0; k < CHUNK; ++k) {
            int e = tid + (k << 10);
            if (e < NFLAT) {
                float s = sc[e];
                unsigned key = (s > SCORE_T) ? __float_as_uint(s) : 0u;
                if (key > pivot) {
                    sm64[wg++] = ((unsigned long long)(key ^ 0xFFFFFFFFu) << 32) | (unsigned)e;
                } else if (fastpath && key == pivot) {
                    sm64[G + we] = ((unsigned long long)(key ^ 0xFFFFFFFFu) << 32) | (unsigned)e;
                    we++;
                }
            }
        }
    }
    if (!fastpath) {
        /* rare: equals truncated -> must take lowest flat indices; contiguous order */
        int ce2 = 0;
        for (int k = 0; k < CHUNK; ++k) {
            int e = tid * CHUNK + k;
            if (e < NFLAT) {
                float s = sc[e];
                unsigned key = (s > SCORE_T) ? __float_as_uint(s) : 0u;
                ce2 += (key == pivot);
            }
        }
        int eoff2 = blk_excl_scan(ce2, tid, wtmp);
        int we = eoff2;
        for (int k = 0; k < CHUNK; ++k) {
            int e = tid * CHUNK + k;
            if (e < NFLAT) {
                float s = sc[e];
                unsigned key = (s > SCORE_T) ? __float_as_uint(s) : 0u;
                if (key == pivot) {
                    int pos = G + we;
                    we++;
                    if (pos < KCAND)
                        sm64[pos] = ((unsigned long long)(key ^ 0xFFFFFFFFu) << 32) | (unsigned)e;
                }
            }
        }
    }
    __syncthreads();

    /* bitonic sort ascending on (~val, idx) => val desc, idx asc on ties.
       Strides >=32 go through shared; strides <=16 are warp-register shfl stages. */
    for (int k2 = 2; k2 <= KCAND; k2 <<= 1) {
        for (int j = k2 >> 1; j >= 32; j >>= 1) {
            int ixj = tid ^ j;
            if (ixj > tid) {
                unsigned long long a = sm64[tid], c = sm64[ixj];
                bool up = ((tid & k2) == 0);
                if ((a > c) == up) { sm64[tid] = c; sm64[ixj] = a; }
            }
            __syncthreads();
        }
        {
            unsigned long long a = sm64[tid];
            bool up = ((tid & k2) == 0) || (k2 == KCAND);
            int j0 = (k2 >> 1 < 16) ? (k2 >> 1) : 16;
            #pragma unroll
            for (int j = 16; j > 0; j >>= 1) {
                if (j <= j0) {
                    unsigned long long c = __shfl_xor_sync(0xffffffffu, a, j);
                    bool keepmin = (((tid & j) == 0) == up);
                    bool amin = (a < c);
                    a = (keepmin == amin) ? a : c;
                }
            }
            sm64[tid] = a;
            __syncthreads();
        }
    }

    /* finalize candidate r = tid */
    unsigned long long v = sm64[tid];
    unsigned key = (unsigned)(v >> 32) ^ 0xFFFFFFFFu;
    int idx = (int)(v & 0xFFFFFFFFu);
    float val = __uint_as_float(key);
    int cls  = idx % NCLS;
    int prop = idx / NCLS;

    float h = (float)hw[b * 2 + 0];
    float w = (float)hw[b * 2 + 1];
    const float* bp = boxes + ((size_t)(b * NPROP + prop) * NCLS + cls) * 4;
    float x1 = fminf(fmaxf(bp[0], 0.0f), w);
    float y1 = fminf(fmaxf(bp[1], 0.0f), h);
    float x2 = fminf(fmaxf(bp[2], 0.0f), w);
    float y2 = fminf(fmaxf(bp[3], 0.0f), h);
    float off = (float)cls * 4096.0f;
    x1 += off; y1 += off; x2 += off; y2 += off;

    g_box[b][tid][0] = x1; g_box[b][tid][1] = y1;
    g_box[b][tid][2] = x2; g_box[b][tid][3] = y2;
    g_area[b][tid] = (x2 - x1) * (y2 - y1);
    g_val[b][tid]  = val;
    g_prop[b][tid] = prop;

    /* ---- build per-class member lists (stable in candidate order) ---- */
    for (int i = tid; i < NCLS * 32; i += 1024) ((unsigned short*)h2)[i] = 0;
    __syncthreads();

    unsigned pm = __match_any_sync(0xffffffffu, cls);
    int leader = __ffs(pm) - 1;
    int intra  = __popc(pm & ((1u << lane) - 1));
    if (lane == leader) h2[cls][wid] = (unsigned short)__popc(pm);
    __syncthreads();

    if (tid < NCLS) {
        int acc = 0;
        #pragma unroll
        for (int w2 = 0; w2 < 32; ++w2) {
            int t = h2[tid][w2];
            h2[tid][w2] = (unsigned short)acc;
            acc += t;
        }
        sh_cnt[tid] = acc;
    }
    __syncthreads();
    if (tid == 0) {
        int acc = 0, acc2 = 0;
        for (int c = 0; c < NCLS; ++c) {
            sh_cstart[c] = acc;
            sh_coff[c]   = acc2;
            int n = sh_cnt[c];
            acc  += n;
            acc2 += n * n;
        }
        sh_cstart[NCLS] = acc;
        sh_coff[NCLS]   = acc2;
    }
    __syncthreads();

    int pos = sh_cstart[cls] + (int)h2[cls][wid] + intra;
    g_member[b][pos] = tid;
    if (tid <= NCLS) {
        g_cstart[b][tid] = sh_cstart[tid];
        g_coff[b][tid]   = sh_coff[tid];
        if (tid < NCLS) g_cnt[b][tid] = sh_cnt[tid];
    }
}

/* ---------------- kernel 3: same-class pair threshold counts ------------- */
__global__ void k_iou_cls()
{
    int c = blockIdx.x;
    int b = blockIdx.y;
    int n     = g_cnt[b][c];
    int start = g_cstart[b][c];
    int base  = g_coff[b][c];
    int total = n * n;

    const float4* gb = (const float4*)g_box[b];
    unsigned char* M = &g_cmat[b][base];

    for (int p = threadIdx.x; p < total; p += blockDim.x) {
        int q = p / n;
        int r = p - q * n;
        int gq = g_member[b][start + q];
        int gr = g_member[b][start + r];
        float4 bq = gb[gq];
        float4 br = gb[gr];
        float iw = fminf(bq.z, br.z) - fmaxf(bq.x, br.x);
        float ih = fminf(bq.w, br.w) - fmaxf(bq.y, br.y);
        iw = fmaxf(iw, 0.0f);
        ih = fmaxf(ih, 0.0f);
        float inter = iw * ih;
        float uni = g_area[b][gq] + g_area[b][gr] - inter;
        float iou = (uni > 0.0f) ? (inter / uni) : 0.0f;
        int cc = 0;
        cc += (iou > 0.001f); cc += (iou > 0.101f); cc += (iou > 0.201f);
        cc += (iou > 0.301f); cc += (iou > 0.401f); cc += (iou > 0.501f);
        cc += (iou > 0.601f); cc += (iou > 0.701f); cc += (iou > 0.801f);
        cc += (iou > 0.901f);
        M[p] = (unsigned char)cc;
    }
}

/* ------ kernel 4: per-(thresh,class) greedy NMS + select + gather -------- */
__global__ void __launch_bounds__(1024) k_nms_final(const float* __restrict__ feats,
                                                    float* __restrict__ out)
{
    int b = blockIdx.x;
    int tid = threadIdx.x;

    __shared__ unsigned keepw[NTH][32];
    __shared__ int cnt_t[NTH];
    __shared__ int selp[6];
    __shared__ int sh_tsel;

    for (int i = tid; i < NTH * 32; i += 1024) ((unsigned*)keepw)[i] = 0;
    if (tid < NTH) cnt_t[tid] = 0;
    __syncthreads();

    if (tid < NTH * NCLS) {
        int t = tid / NCLS;
        int c = tid % NCLS;
        int n = g_cnt[b][c];
        if (n > 0) {
            int start = g_cstart[b][c];
            const unsigned char* M = &g_cmat[b][g_coff[b][c]];
            int keptc = 0;
            if (n <= 64) {
                unsigned long long sup = 0;
                for (int r = 0; r < n; ++r) {
                    if ((sup >> r) & 1ULL) continue;
                    int gi = g_member[b][start + r];
                    if (!(g_val[b][gi] > SCORE_T)) continue;
                    ++keptc;
                    atomicOr(&keepw[t][gi >> 5], 1u << (gi & 31));
                    const unsigned char* row = M + r * n;
                    for (int rr = r + 1; rr < n; ++rr)
                        if ((int)row[rr] > t) sup |= 1ULL << rr;
                }
            } else {
                unsigned long long sup[16];
                #pragma unroll
                for (int w2 = 0; w2 < 16; ++w2) sup[w2] = 0;
                for (int r = 0; r < n; ++r) {
                    if ((sup[r >> 6] >> (r & 63)) & 1ULL) continue;
                    int gi = g_member[b][start + r];
                    if (!(g_val[b][gi] > SCORE_T)) continue;
                    ++keptc;
                    atomicOr(&keepw[t][gi >> 5], 1u << (gi & 31));
                    const unsigned char* row = M + r * n;
                    for (int rr = r + 1; rr < n; ++rr)
                        if ((int)row[rr] > t) sup[rr >> 6] |= 1ULL << (rr & 63);
                }
            }
            if (keptc) atomicAdd(&cnt_t[t], keptc);
        }
    }
    __syncthreads();

    if (tid == 0) {
        int tsel = NTH - 1;
        for (int q = 0; q < NTH; ++q)
            if (cnt_t[q] >= 6) { tsel = q; break; }
        sh_tsel = tsel;
        /* kept candidates in ascending gi == descending score, idx-asc ties */
        int found = 0;
        for (int w2 = 0; w2 < 32 && found < 6; ++w2) {
            unsigned m = keepw[tsel][w2];
            while (m && found < 6) {
                int bpos = __ffs(m) - 1;
                m &= m - 1;
                selp[found++] = g_prop[b][w2 * 32 + bpos];
            }
        }
        if (found < 6) {   /* pad with lowest-index non-kept (-inf ties) */
            for (int gi = 0; gi < KCAND && found < 6; ++gi)
                if (!((keepw[tsel][gi >> 5] >> (gi & 31)) & 1u))
                    selp[found++] = g_prop[b][gi];
        }
    }
    __syncthreads();

    /* fused feature gather: out[b][d][j] = feats[b][selp[j]][d] */
    int p0 = selp[0], p1 = selp[1], p2 = selp[2];
    int p3 = selp[3], p4 = selp[4], p5 = selp[5];
    const float* fb = feats + (size_t)b * NPROP * DFEAT;
    float* ob = out + (size_t)b * DFEAT * 6;
    for (int d = tid; d < DFEAT; d += 1024) {
        float* o = ob + d * 6;
        o[0] = fb[(size_t)p0 * DFEAT + d];
        o[1] = fb[(size_t)p1 * DFEAT + d];
        o[2] = fb[(size_t)p2 * DFEAT + d];
        o[3] = fb[(size_t)p3 * DFEAT + d];
        o[4] = fb[(size_t)p4 * DFEAT + d];
        o[5] = fb[(size_t)p5 * DFEAT + d];
    }
}

/* ---------------- launch -------------------------------------------------- */
extern "C" void kernel_launch(void* const* d_in, const int* in_sizes, int n_in,
                              void* d_out, int out_size)
{
    (void)in_sizes; (void)n_in; (void)out_size;
    const float* logits = (const float*)d_in[0];
    const float* boxes  = (const float*)d_in[1];
    const float* feats  = (const float*)d_in[2];
    const int*   hw     = (const int*)  d_in[3];
    float* out = (float*)d_out;

    k_softmax<<<(BATCH * NPROP + 3) / 4, 128>>>(logits);
    k_select<<<BATCH, 1024>>>(boxes, hw);
    k_iou_cls<<<dim3(NCLS, BATCH), 128>>>();
    k_nms_final<<<BATCH, 1024>>>(feats, out);
}

// round 5
// speedup vs baseline: 2.0962x; 1.3966x over previous
#include <cuda_runtime.h>
#include <math.h>

#define BATCH 8
#define NPROP 1000
#define NCLS  80
#define NLOG  81
#define DFEAT 2048
#define KCAND 1024
#define NFLAT (NPROP*NCLS)   /* 80000 */
#define NTH   10
#define SCORE_T 1e-4f
#define CBUF   4096
#define NHBLK  16
#define HELEM  (NFLAT/NHBLK) /* 5000 */
#define SH_CMAT_CAP 30720

typedef unsigned long long u64;

/* ---------------- scratch (static device globals; no allocation) -------- */
__device__ unsigned g_keys[BATCH][NFLAT];
__device__ int      g_hist[BATCH][2048];
__device__ int      g_ccount[BATCH];
__device__ u64      g_cbuf[BATCH][CBUF];
__device__ float    g_boxv[BATCH][KCAND][4];
__device__ float    g_area[BATCH][KCAND];
__device__ int      g_prop[BATCH][KCAND];
__device__ int      g_member[BATCH][KCAND];
__device__ int      g_cstart[BATCH][NCLS + 1];
__device__ int      g_cnt[BATCH][NCLS];
__device__ unsigned char g_cls[BATCH][KCAND];
__device__ short    g_loc[BATCH][KCAND];
__device__ unsigned g_validw[BATCH][32];
__device__ unsigned char g_cmat_ovf[BATCH][1 << 20];

/* ------- kernel 1: softmax -> thresholded key bits (+ zero scratch) ----- */
__global__ void k_softmax(const float* __restrict__ logits)
{
    /* zero histograms / counters for this replay */
    if (blockIdx.x < 128) {
        ((int*)g_hist)[blockIdx.x * 128 + threadIdx.x] = 0;
    } else if (blockIdx.x == 128 && threadIdx.x < BATCH) {
        g_ccount[threadIdx.x] = 0;
    }

    int gw   = blockIdx.x * (blockDim.x >> 5) + (threadIdx.x >> 5);
    int lane = threadIdx.x & 31;
    if (gw >= BATCH * NPROP) return;
    int b = gw / NPROP, r = gw % NPROP;
    const float* p = logits + (size_t)(b * NPROP + r) * NLOG;

    float v0 = p[lane];
    float v1 = p[lane + 32];
    float v2 = (lane + 64 < NLOG) ? p[lane + 64] : -INFINITY;
    float m = fmaxf(fmaxf(v0, v1), v2);
    #pragma unroll
    for (int o = 16; o; o >>= 1) m = fmaxf(m, __shfl_xor_sync(0xffffffffu, m, o));
    float e0 = expf(v0 - m);
    float e1 = expf(v1 - m);
    float e2 = (lane + 64 < NLOG) ? expf(v2 - m) : 0.0f;
    float s = e0 + e1 + e2;
    #pragma unroll
    for (int o = 16; o; o >>= 1) s += __shfl_xor_sync(0xffffffffu, s, o);

    unsigned* out = &g_keys[b][r * NCLS];
    float p0 = e0 / s, p1 = e1 / s, p2 = e2 / s;
    out[lane]      = (p0 > SCORE_T) ? __float_as_uint(p0) : 0u;
    out[lane + 32] = (p1 > SCORE_T) ? __float_as_uint(p1) : 0u;
    if (lane + 64 < NCLS) out[lane + 64] = (p2 > SCORE_T) ? __float_as_uint(p2) : 0u;
}

/* ---------------- kernel 2: 11-bit histogram (bits [31:21]) ------------- */
__global__ void k_hist()
{
    int b = blockIdx.y;
    int tid = threadIdx.x;
    __shared__ int h[2048];
    for (int i = tid; i < 2048; i += 256) h[i] = 0;
    __syncthreads();

    int base = blockIdx.x * HELEM;
    for (int i = base + tid; i < base + HELEM; i += 256) {
        unsigned key = g_keys[b][i];
        atomicAdd(&h[key >> 21], 1);
    }
    __syncthreads();
    for (int i = tid; i < 2048; i += 256) {
        int v = h[i];
        if (v) atomicAdd(&g_hist[b][i], v);
    }
}

/* ----- kernel 3: compact all elements with top11 >= pivot bin ----------- */
__global__ void k_compact()
{
    int b = blockIdx.y;
    int tid = threadIdx.x, lane = tid & 31, wid = tid >> 5;
    __shared__ int sh_d1;

    if (wid == 0) {
        int run = 0, found = 0;
        for (int g = 0; g < 64; ++g) {
            int bin = 2047 - (g * 32 + lane);
            int c = g_hist[b][bin];
            int inc = c;
            #pragma unroll
            for (int o = 1; o < 32; o <<= 1) {
                int u = __shfl_up_sync(0xffffffffu, inc, o);
                if (lane >= o) inc += u;
            }
            int cum = run + inc;
            unsigned bal = __ballot_sync(0xffffffffu, cum >= KCAND);
            if (bal) {
                int fl = __ffs(bal) - 1;
                if (lane == fl) sh_d1 = bin;
                found = 1;
            }
            run += __shfl_sync(0xffffffffu, inc, 31);
            if (found) break;
        }
        if (!found && lane == 0) sh_d1 = 0;
    }
    __syncthreads();
    unsigned d1 = (unsigned)sh_d1;

    int base = blockIdx.x * HELEM;
    int iters = (HELEM + 255) / 256;
    for (int k = 0; k < iters; ++k) {
        int i = base + tid + k * 256;
        bool in = (i < base + HELEM);
        unsigned key = in ? g_keys[b][i] : 0u;
        bool q = in && ((key >> 21) >= d1);
        unsigned bal = __ballot_sync(0xffffffffu, q);
        if (bal) {
            int ldr = __ffs(bal) - 1;
            int pos = 0;
            if (lane == ldr) pos = atomicAdd(&g_ccount[b], __popc(bal));
            pos = __shfl_sync(0xffffffffu, pos, ldr);
            if (q) {
                int my = pos + __popc(bal & ((1u << lane) - 1));
                if (my < CBUF)
                    g_cbuf[b][my] = ((u64)(key ^ 0xFFFFFFFFu) << 32) | (unsigned)i;
            }
        }
    }
}

/* ----- kernel 4: sort candidates, finalize top-1024, class lists -------- */
__global__ void __launch_bounds__(1024) k_final(const float* __restrict__ boxes,
                                                const int*   __restrict__ hw)
{
    int b = blockIdx.x;
    int tid = threadIdx.x, lane = tid & 31, wid = tid >> 5;

    __shared__ u64 sm64[CBUF];
    __shared__ unsigned short h2[NCLS][32];
    __shared__ int sh_cnt[NCLS];
    __shared__ int sh_cstart[NCLS + 1];

    int cnt = g_ccount[b];
    if (cnt > CBUF) cnt = CBUF;
    int M = 1024;
    while (M < cnt) M <<= 1;
    int E = M >> 10;

    for (int i = tid; i < M; i += 1024)
        sm64[i] = (i < cnt) ? g_cbuf[b][i] : 0xFFFFFFFFFFFFFFFFULL;
    __syncthreads();

    /* hybrid bitonic sort ascending on (~val, idx) */
    for (int k2 = 2; k2 <= M; k2 <<= 1) {
        for (int j = k2 >> 1; j >= 32; j >>= 1) {
            for (int e = 0; e < E; ++e) {
                int i = tid + (e << 10);
                int ixj = i ^ j;
                if (ixj > i) {
                    u64 a = sm64[i], c = sm64[ixj];
                    bool up = ((i & k2) == 0);
                    if ((a > c) == up) { sm64[i] = c; sm64[ixj] = a; }
                }
            }
            __syncthreads();
        }
        int j0 = ((k2 >> 1) < 16) ? (k2 >> 1) : 16;
        for (int e = 0; e < E; ++e) {
            int i = tid + (e << 10);
            u64 a = sm64[i];
            bool up = ((i & k2) == 0);
            #pragma unroll
            for (int j = 16; j > 0; j >>= 1) {
                if (j <= j0) {
                    u64 c = __shfl_xor_sync(0xffffffffu, a, j);
                    bool keepmin = (((i & j) == 0) == up);
                    bool amin = (a < c);
                    a = (keepmin == amin) ? a : c;
                }
            }
            sm64[i] = a;
        }
        __syncthreads();
    }

    /* finalize candidate gi = tid */
    u64 v = sm64[tid];
    unsigned key = (unsigned)(v >> 32) ^ 0xFFFFFFFFu;
    unsigned idxu = (unsigned)(v & 0xFFFFFFFFu);
    int idx = (idxu < NFLAT) ? (int)idxu : 0;
    int cls  = idx % NCLS;
    int prop = idx / NCLS;

    float h = (float)hw[b * 2 + 0];
    float w = (float)hw[b * 2 + 1];
    const float* bp = boxes + ((size_t)(b * NPROP + prop) * NCLS + cls) * 4;
    float x1 = fminf(fmaxf(bp[0], 0.0f), w);
    float y1 = fminf(fmaxf(bp[1], 0.0f), h);
    float x2 = fminf(fmaxf(bp[2], 0.0f), w);
    float y2 = fminf(fmaxf(bp[3], 0.0f), h);
    float off = (float)cls * 4096.0f;
    x1 += off; y1 += off; x2 += off; y2 += off;

    g_boxv[b][tid][0] = x1; g_boxv[b][tid][1] = y1;
    g_boxv[b][tid][2] = x2; g_boxv[b][tid][3] = y2;
    g_area[b][tid] = (x2 - x1) * (y2 - y1);
    g_prop[b][tid] = prop;

    unsigned vb = __ballot_sync(0xffffffffu, key != 0u);
    if (lane == 0) g_validw[b][wid] = vb;

    /* ---- per-class member lists (stable in candidate order) ---- */
    for (int i = tid; i < NCLS * 32; i += 1024) ((unsigned short*)h2)[i] = 0;
    __syncthreads();

    unsigned pm = __match_any_sync(0xffffffffu, cls);
    int leader = __ffs(pm) - 1;
    int intra  = __popc(pm & ((1u << lane) - 1));
    if (lane == leader) h2[cls][wid] = (unsigned short)__popc(pm);
    __syncthreads();

    if (tid < NCLS) {
        int acc = 0;
        #pragma unroll
        for (int w2 = 0; w2 < 32; ++w2) {
            int t = h2[tid][w2];
            h2[tid][w2] = (unsigned short)acc;
            acc += t;
        }
        sh_cnt[tid] = acc;
    }
    __syncthreads();
    if (tid == 0) {
        int acc = 0;
        for (int c = 0; c < NCLS; ++c) {
            sh_cstart[c] = acc;
            acc += sh_cnt[c];
        }
        sh_cstart[NCLS] = acc;
    }
    __syncthreads();

    int pos = sh_cstart[cls] + (int)h2[cls][wid] + intra;
    g_member[b][pos] = tid;
    g_cls[b][tid] = (unsigned char)cls;
    g_loc[b][tid] = (short)(pos - sh_cstart[cls]);
    if (tid <= NCLS) {
        g_cstart[b][tid] = sh_cstart[tid];
        if (tid < NCLS) g_cnt[b][tid] = sh_cnt[tid];
    }
}

/* ----- kernel 5: fused IOU + per-(thresh,class) NMS + select + gather --- */
__global__ void __launch_bounds__(1024) k_nms(const float* __restrict__ feats,
                                              float* __restrict__ out)
{
    int b = blockIdx.x;
    int tid = threadIdx.x, lane = tid & 31, wid = tid >> 5;

    __shared__ unsigned char sh_cmat[SH_CMAT_CAP];
    __shared__ u64 sh_mask[NTH][NCLS];
    __shared__ int sh_member[KCAND];
    __shared__ unsigned sh_validw[32];
    __shared__ unsigned keepw[NTH][32];
    __shared__ unsigned keepw2[NTH][32];
    __shared__ int sh_cnt[NCLS];
    __shared__ int sh_cstart[NCLS + 1];
    __shared__ int sh_cmoff[NCLS];
    __shared__ char sh_gmem[NCLS];
    __shared__ int cnt_t[NTH];
    __shared__ int selp[6];
    __shared__ int sh_tsel;

    sh_member[tid] = g_member[b][tid];
    if (tid < NCLS) sh_cnt[tid] = g_cnt[b][tid];
    if (tid >= 64 && tid < 64 + NCLS + 1) sh_cstart[tid - 64] = g_cstart[b][tid - 64];
    if (tid >= 256 && tid < 256 + 32) sh_validw[tid - 256] = g_validw[b][tid - 256];
    for (int i = tid; i < NTH * 32; i += 1024) {
        ((unsigned*)keepw2)[i] = 0;
    }
    if (tid == 0) {
        int accs = 0, accg = 0;
        for (int c = 0; c < NCLS; ++c) {
            int n = sh_cnt[c];
            int sz = n * n;
            if (accs + sz <= SH_CMAT_CAP) { sh_cmoff[c] = accs; sh_gmem[c] = 0; accs += sz; }
            else                          { sh_cmoff[c] = accg; sh_gmem[c] = 1; accg += sz; }
        }
    }
    __syncthreads();

    /* IOU -> per-pair threshold-count bytes */
    const float4* gb = (const float4*)g_boxv[b];
    for (int c = 0; c < NCLS; ++c) {
        int n = sh_cnt[c];
        int tot = n * n;
        if (tot == 0) continue;
        int start = sh_cstart[c];
        unsigned char* Mp = sh_gmem[c] ? &g_cmat_ovf[b][sh_cmoff[c]] : &sh_cmat[sh_cmoff[c]];
        for (int p = tid; p < tot; p += 1024) {
            int q = p / n;
            int r = p - q * n;
            int gq = sh_member[start + q];
            int gr = sh_member[start + r];
            float4 bq = gb[gq];
            float4 br = gb[gr];
            float iw = fminf(bq.z, br.z) - fmaxf(bq.x, br.x);
            float ih = fminf(bq.w, br.w) - fmaxf(bq.y, br.y);
            iw = fmaxf(iw, 0.0f);
            ih = fmaxf(ih, 0.0f);
            float inter = iw * ih;
            float uni = g_area[b][gq] + g_area[b][gr] - inter;
            float iou = (uni > 0.0f) ? (inter / uni) : 0.0f;
            int cc = 0;
            cc += (iou > 0.001f); cc += (iou > 0.101f); cc += (iou > 0.201f);
            cc += (iou > 0.301f); cc += (iou > 0.401f); cc += (iou > 0.501f);
            cc += (iou > 0.601f); cc += (iou > 0.701f); cc += (iou > 0.801f);
            cc += (iou > 0.901f);
            Mp[p] = (unsigned char)cc;
        }
    }
    __syncthreads();

    /* phase 1: greedy chains; lanes share a class (t = tid%10, c = tid/10) */
    if (tid < NTH * NCLS) {
        int t = tid % NTH;
        int c = tid / NTH;
        int n = sh_cnt[c];
        int start = sh_cstart[c];
        const unsigned char* Mp = sh_gmem[c] ? &g_cmat_ovf[b][sh_cmoff[c]] : &sh_cmat[sh_cmoff[c]];
        u64 kept = 0;
        if (n > 0 && n <= 64) {
            u64 sup = 0;
            for (int r = 0; r < n; ++r) {
                if ((sup >> r) & 1ULL) continue;
                int gi = sh_member[start + r];
                if (!((sh_validw[gi >> 5] >> (gi & 31)) & 1u)) continue;
                kept |= 1ULL << r;
                const unsigned char* row = Mp + r * n;
                for (int rr = r + 1; rr < n; ++rr)
                    if ((int)row[rr] > t) sup |= 1ULL << rr;
            }
        } else if (n > 64) {
            u64 sup[16];
            #pragma unroll
            for (int w2 = 0; w2 < 16; ++w2) sup[w2] = 0;
            for (int r = 0; r < n; ++r) {
                if ((sup[r >> 6] >> (r & 63)) & 1ULL) continue;
                int gi = sh_member[start + r];
                if (!((sh_validw[gi >> 5] >> (gi & 31)) & 1u)) continue;
                atomicOr(&keepw2[t][gi >> 5], 1u << (gi & 31));
                const unsigned char* row = Mp + r * n;
                for (int rr = r + 1; rr < n; ++rr)
                    if ((int)row[rr] > t) sup[rr >> 6] |= 1ULL << (rr & 63);
            }
            kept = 0; /* big class handled via keepw2 */
        }
        sh_mask[t][c] = kept;
    }
    __syncthreads();

    /* phase 2: ballot-assemble keep words in candidate (gi) order */
    {
        int c = (int)g_cls[b][tid];
        int r = (int)g_loc[b][tid];
        #pragma unroll
        for (int t = 0; t < NTH; ++t) {
            int bit = (r < 64) ? (int)((sh_mask[t][c] >> r) & 1ULL) : 0;
            unsigned bal = __ballot_sync(0xffffffffu, bit);
            if (lane == 0) keepw[t][wid] = bal | keepw2[t][wid];
        }
    }
    __syncthreads();

    if (tid < NTH) {
        int s = 0;
        #pragma unroll
        for (int w2 = 0; w2 < 32; ++w2) s += __popc(keepw[tid][w2]);
        cnt_t[tid] = s;
    }
    __syncthreads();

    if (tid == 0) {
        int tsel = NTH - 1;
        for (int q = 0; q < NTH; ++q)
            if (cnt_t[q] >= 6) { tsel = q; break; }
        sh_tsel = tsel;
        int found = 0;
        for (int w2 = 0; w2 < 32 && found < 6; ++w2) {
            unsigned m = keepw[tsel][w2];
            while (m && found < 6) {
                int bpos = __ffs(m) - 1;
                m &= m - 1;
                selp[found++] = g_prop[b][w2 * 32 + bpos];
            }
        }
        if (found < 6) {
            for (int gi = 0; gi < KCAND && found < 6; ++gi)
                if (!((keepw[tsel][gi >> 5] >> (gi & 31)) & 1u))
                    selp[found++] = g_prop[b][gi];
        }
    }
    __syncthreads();

    /* fused feature gather: out[b][d][j] = feats[b][selp[j]][d] */
    int p0 = selp[0], p1 = selp[1], p2 = selp[2];
    int p3 = selp[3], p4 = selp[4], p5 = selp[5];
    const float* fb = feats + (size_t)b * NPROP * DFEAT;
    float* ob = out + (size_t)b * DFEAT * 6;
    for (int d = tid; d < DFEAT; d += 1024) {
        float* o = ob + d * 6;
        o[0] = fb[(size_t)p0 * DFEAT + d];
        o[1] = fb[(size_t)p1 * DFEAT + d];
        o[2] = fb[(size_t)p2 * DFEAT + d];
        o[3] = fb[(size_t)p3 * DFEAT + d];
        o[4] = fb[(size_t)p4 * DFEAT + d];
        o[5] = fb[(size_t)p5 * DFEAT + d];
    }
}

/* ---------------- launch -------------------------------------------------- */
extern "C" void kernel_launch(void* const* d_in, const int* in_sizes, int n_in,
                              void* d_out, int out_size)
{
    (void)in_sizes; (void)n_in; (void)out_size;
    const float* logits = (const float*)d_in[0];
    const float* boxes  = (const float*)d_in[1];
    const float* feats  = (const float*)d_in[2];
    const int*   hw     = (const int*)  d_in[3];
    float* out = (float*)d_out;

    k_softmax<<<(BATCH * NPROP + 3) / 4, 128>>>(logits);
    k_hist<<<dim3(NHBLK, BATCH), 256>>>();
    k_compact<<<dim3(NHBLK, BATCH), 256>>>();
    k_final<<<BATCH, 1024>>>(boxes, hw);
    k_nms<<<BATCH, 1024>>>(feats, out);
}

// round 7
// speedup vs baseline: 2.1016x; 1.0025x over previous
#include <cuda_runtime.h>
#include <math.h>

#define BATCH 8
#define NPROP 1000
#define NCLS  80
#define NLOG  81
#define DFEAT 2048
#define KCAND 1024
#define NFLAT (NPROP*NCLS)   /* 80000 */
#define NTH   10
#define SCORE_T 1e-4f
#define CBUF   4096
#define BPI    16            /* front blocks per image */
#define NBLK1  (BATCH*BPI)   /* 128 */
#define CMAT_CAP (CBUF*8)    /* 32768 bytes, reuse of sort buffer */

typedef unsigned long long u64;

/* ---------------- scratch (static device globals; no allocation) -------- */
__device__ int      g_hist[BATCH][2048];   /* zeroed by k_back for next replay */
__device__ int      g_ccount[BATCH];
__device__ u64      g_cbuf[BATCH][CBUF];
__device__ float    g_boxv[BATCH][KCAND][4];
__device__ int      g_prop[BATCH][KCAND];
__device__ unsigned char g_cmat_ovf[BATCH][1 << 20];

/* ------- device-wide sense barrier (128 blocks, all wave-1 resident) ----- */
__device__ unsigned g_ctr = 0;
__device__ unsigned g_gen = 0;
__device__ __forceinline__ void gridbar(unsigned nb)
{
    __syncthreads();
    if (threadIdx.x == 0) {
        __threadfence();
        unsigned gen = atomicAdd(&g_gen, 0u);
        if (atomicAdd(&g_ctr, 1u) == nb - 1u) {
            g_ctr = 0;
            __threadfence();
            atomicExch(&g_gen, gen + 1u);
        } else {
            while (atomicAdd(&g_gen, 0u) == gen) { __nanosleep(32); }
        }
        __threadfence();
    }
    __syncthreads();
}

/* ------ kernel 1: softmax -> keys(shared) + hist -> barrier -> compact --- */
__global__ void __launch_bounds__(256) k_front(const float* __restrict__ logits)
{
    int blk = blockIdx.x;
    int b  = blk / BPI;
    int sb = blk % BPI;
    int r0   = sb * 62 + (sb < 8 ? sb : 8);
    int rows = 62 + (sb < 8 ? 1 : 0);
    int nel  = rows * NCLS;

    __shared__ unsigned sh_keys[63 * NCLS];  /* 5040 */
    __shared__ int sh_hist[2048];
    __shared__ int sh_d1;

    int tid = threadIdx.x, lane = tid & 31, wid = tid >> 5;

    for (int i = tid; i < 2048; i += 256) sh_hist[i] = 0;
    __syncthreads();

    /* softmax: one warp per row */
    for (int r = wid; r < rows; r += 8) {
        const float* p = logits + (size_t)(b * NPROP + r0 + r) * NLOG;
        float v0 = p[lane];
        float v1 = p[lane + 32];
        float v2 = (lane + 64 < NLOG) ? p[lane + 64] : -INFINITY;
        float m = fmaxf(fmaxf(v0, v1), v2);
        #pragma unroll
        for (int o = 16; o; o >>= 1) m = fmaxf(m, __shfl_xor_sync(0xffffffffu, m, o));
        float e0 = expf(v0 - m);
        float e1 = expf(v1 - m);
        float e2 = (lane + 64 < NLOG) ? expf(v2 - m) : 0.0f;
        float s = e0 + e1 + e2;
        #pragma unroll
        for (int o = 16; o; o >>= 1) s += __shfl_xor_sync(0xffffffffu, s, o);
        float p0 = e0 / s, p1 = e1 / s, p2 = e2 / s;
        unsigned k0 = (p0 > SCORE_T) ? __float_as_uint(p0) : 0u;
        unsigned k1 = (p1 > SCORE_T) ? __float_as_uint(p1) : 0u;
        unsigned k2 = (p2 > SCORE_T) ? __float_as_uint(p2) : 0u;
        sh_keys[r * NCLS + lane]      = k0;
        sh_keys[r * NCLS + lane + 32] = k1;
        atomicAdd(&sh_hist[k0 >> 21], 1);
        atomicAdd(&sh_hist[k1 >> 21], 1);
        if (lane + 64 < NCLS) {
            sh_keys[r * NCLS + lane + 64] = k2;
            atomicAdd(&sh_hist[k2 >> 21], 1);
        }
    }
    __syncthreads();

    for (int i = tid; i < 2048; i += 256) {
        int v = sh_hist[i];
        if (v) atomicAdd(&g_hist[b][i], v);
    }

    gridbar(NBLK1);

    /* pivot: highest bin where cumulative (from top) reaches KCAND */
    if (wid == 0) {
        int run = 0, found = 0;
        for (int g = 0; g < 64; ++g) {
            int bin = 2047 - (g * 32 + lane);
            int c = g_hist[b][bin];
            int inc = c;
            #pragma unroll
            for (int o = 1; o < 32; o <<= 1) {
                int u = __shfl_up_sync(0xffffffffu, inc, o);
                if (lane >= o) inc += u;
            }
            int cum = run + inc;
            unsigned bal = __ballot_sync(0xffffffffu, cum >= KCAND);
            if (bal) {
                int fl = __ffs(bal) - 1;
                if (lane == fl) sh_d1 = bin;
                found = 1;
            }
            run += __shfl_sync(0xffffffffu, inc, 31);
            if (found) break;
        }
        if (!found && lane == 0) sh_d1 = 0;
    }
    __syncthreads();
    unsigned d1 = (unsigned)sh_d1;

    /* compact candidates (top11 >= d1) from shared keys */
    int iters = (nel + 255) / 256;
    for (int k = 0; k < iters; ++k) {
        int i = tid + k * 256;
        bool in = (i < nel);
        unsigned key = in ? sh_keys[i] : 0u;
        bool q = in && ((key >> 21) >= d1);
        unsigned bal = __ballot_sync(0xffffffffu, q);
        if (bal) {
            int ldr = __ffs(bal) - 1;
            int pos = 0;
            if (lane == ldr) pos = atomicAdd(&g_ccount[b], __popc(bal));
            pos = __shfl_sync(0xffffffffu, pos, ldr);
            if (q) {
                int my = pos + __popc(bal & ((1u << lane) - 1));
                if (my < CBUF) {
                    unsigned idx = (unsigned)(r0 * NCLS + i);
                    g_cbuf[b][my] = ((u64)(key ^ 0xFFFFFFFFu) << 32) | idx;
                }
            }
        }
    }
}

/* ------ kernel 2: sort + finalize + class lists + IOU + NMS + gather ----- */
__global__ void __launch_bounds__(1024) k_back(const float* __restrict__ boxes,
                                               const int*   __restrict__ hw,
                                               const float* __restrict__ feats,
                                               float* __restrict__ out)
{
    int b = blockIdx.x;
    int tid = threadIdx.x, lane = tid & 31, wid = tid >> 5;

    __shared__ u64 sA[CBUF];                 /* 32KB: sort buffer, then cmat */
    __shared__ union {
        unsigned short h2[NCLS][32];         /* class histogram (finalize) */
        u64 mask[NTH][NCLS];                 /* NMS keep masks (later) */
    } uB;
    __shared__ short sh_member[KCAND];
    __shared__ unsigned char sh_cls[KCAND];
    __shared__ short sh_loc[KCAND];
    __shared__ unsigned sh_validw[32];
    __shared__ unsigned keepw[NTH][32];
    __shared__ unsigned keepw2[NTH][32];
    __shared__ int sh_cnt[NCLS];
    __shared__ int sh_cstart[NCLS + 1];
    __shared__ int sh_cmoff[NCLS];
    __shared__ char sh_gm[NCLS];
    __shared__ int cnt_t[NTH];
    __shared__ int selp[6];
    __shared__ int s_cnt;

    if (tid == 0) s_cnt = g_ccount[b];
    __syncthreads();
    int cnt = s_cnt;
    if (cnt > CBUF) cnt = CBUF;
    int M = 1024;
    while (M < cnt) M <<= 1;
    int E = M >> 10;

    for (int i = tid; i < M; i += 1024)
        sA[i] = (i < cnt) ? g_cbuf[b][i] : 0xFFFFFFFFFFFFFFFFULL;

    /* reset replay scratch (g_ccount already read; g_hist consumed) */
    if (tid == 0) g_ccount[b] = 0;
    g_hist[b][tid] = 0;
    g_hist[b][tid + 1024] = 0;
    __syncthreads();

    /* hybrid bitonic sort ascending on (~val, idx) */
    for (int k2 = 2; k2 <= M; k2 <<= 1) {
        for (int j = k2 >> 1; j >= 32; j >>= 1) {
            for (int e = 0; e < E; ++e) {
                int i = tid + (e << 10);
                int ixj = i ^ j;
                if (ixj > i) {
                    u64 a = sA[i], c = sA[ixj];
                    bool up = ((i & k2) == 0);
                    if ((a > c) == up) { sA[i] = c; sA[ixj] = a; }
                }
            }
            __syncthreads();
        }
        int j0 = ((k2 >> 1) < 16) ? (k2 >> 1) : 16;
        for (int e = 0; e < E; ++e) {
            int i = tid + (e << 10);
            u64 a = sA[i];
            bool up = ((i & k2) == 0);
            #pragma unroll
            for (int j = 16; j > 0; j >>= 1) {
                if (j <= j0) {
                    u64 c = __shfl_xor_sync(0xffffffffu, a, j);
                    bool keepmin = (((i & j) == 0) == up);
                    bool amin = (a < c);
                    a = (keepmin == amin) ? a : c;
                }
            }
            sA[i] = a;
        }
        __syncthreads();
    }

    /* finalize candidate gi = tid (top-1024) */
    u64 v = sA[tid];
    __syncthreads();   /* sA free after this point -> becomes cmat */

    unsigned key = (unsigned)(v >> 32) ^ 0xFFFFFFFFu;
    unsigned idxu = (unsigned)(v & 0xFFFFFFFFu);
    int idx = (idxu < NFLAT) ? (int)idxu : 0;
    int cls  = idx % NCLS;
    int prop = idx / NCLS;

    float h = (float)hw[b * 2 + 0];
    float w = (float)hw[b * 2 + 1];
    const float* bp = boxes + ((size_t)(b * NPROP + prop) * NCLS + cls) * 4;
    float x1 = fminf(fmaxf(bp[0], 0.0f), w);
    float y1 = fminf(fmaxf(bp[1], 0.0f), h);
    float x2 = fminf(fmaxf(bp[2], 0.0f), w);
    float y2 = fminf(fmaxf(bp[3], 0.0f), h);
    float off = (float)cls * 4096.0f;
    x1 += off; y1 += off; x2 += off; y2 += off;

    g_boxv[b][tid][0] = x1; g_boxv[b][tid][1] = y1;
    g_boxv[b][tid][2] = x2; g_boxv[b][tid][3] = y2;
    g_prop[b][tid] = prop;

    unsigned vb = __ballot_sync(0xffffffffu, key != 0u);
    if (lane == 0) sh_validw[wid] = vb;

    /* ---- per-class member lists (stable in candidate order) ---- */
    for (int i = tid; i < NCLS * 32; i += 1024) ((unsigned short*)uB.h2)[i] = 0;
    for (int i = tid; i < NTH * 32; i += 1024) ((unsigned*)keepw2)[i] = 0;
    __syncthreads();

    unsigned pm = __match_any_sync(0xffffffffu, cls);
    int leader = __ffs(pm) - 1;
    int intra  = __popc(pm & ((1u << lane) - 1));
    if (lane == leader) uB.h2[cls][wid] = (unsigned short)__popc(pm);
    __syncthreads();

    if (tid < NCLS) {
        int acc = 0;
        #pragma unroll
        for (int w2 = 0; w2 < 32; ++w2) {
            int t = uB.h2[tid][w2];
            uB.h2[tid][w2] = (unsigned short)acc;
            acc += t;
        }
        sh_cnt[tid] = acc;
    }
    __syncthreads();
    if (tid == 0) {
        int acc = 0, accs = 0, accg = 0;
        for (int c = 0; c < NCLS; ++c) {
            sh_cstart[c] = acc;
            int n = sh_cnt[c];
            acc += n;
            int sz = n * n;
            if (accs + sz <= CMAT_CAP) { sh_cmoff[c] = accs; sh_gm[c] = 0; accs += sz; }
            else                       { sh_cmoff[c] = accg; sh_gm[c] = 1; accg += sz; }
        }
        sh_cstart[NCLS] = acc;
    }
    __syncthreads();

    int posc = sh_cstart[cls] + (int)uB.h2[cls][wid] + intra;
    sh_member[posc] = (short)tid;
    sh_cls[tid] = (unsigned char)cls;
    sh_loc[tid] = (short)(posc - sh_cstart[cls]);
    __syncthreads();   /* h2 done -> uB becomes mask */

    /* ---- IOU -> per-pair threshold-count bytes (into reused sA) ---- */
    unsigned char* cmat = (unsigned char*)sA;
    const float4* gb = (const float4*)g_boxv[b];
    for (int c = 0; c < NCLS; ++c) {
        int n = sh_cnt[c];
        int tot = n * n;
        if (tot == 0) continue;
        int start = sh_cstart[c];
        unsigned char* Mp = sh_gm[c] ? &g_cmat_ovf[b][sh_cmoff[c]] : &cmat[sh_cmoff[c]];
        for (int p = tid; p < tot; p += 1024) {
            int q = p / n;
            int r = p - q * n;
            int gq = (int)sh_member[start + q];
            int gr = (int)sh_member[start + r];
            float4 bq = gb[gq];
            float4 br = gb[gr];
            float iw = fminf(bq.z, br.z) - fmaxf(bq.x, br.x);
            float ih = fminf(bq.w, br.w) - fmaxf(bq.y, br.y);
            iw = fmaxf(iw, 0.0f);
            ih = fmaxf(ih, 0.0f);
            float inter = iw * ih;
            float aq = (bq.z - bq.x) * (bq.w - bq.y);
            float ar = (br.z - br.x) * (br.w - br.y);
            float uni = aq + ar - inter;
            float iou = (uni > 0.0f) ? (inter / uni) : 0.0f;
            int cc = 0;
            cc += (iou > 0.001f); cc += (iou > 0.101f); cc += (iou > 0.201f);
            cc += (iou > 0.301f); cc += (iou > 0.401f); cc += (iou > 0.501f);
            cc += (iou > 0.601f); cc += (iou > 0.701f); cc += (iou > 0.801f);
            cc += (iou > 0.901f);
            Mp[p] = (unsigned char)cc;
        }
    }
    __syncthreads();

    /* phase 1: greedy chains; lanes share a class (t = tid%10, c = tid/10) */
    if (tid < NTH * NCLS) {
        int t = tid % NTH;
        int c = tid / NTH;
        int n = sh_cnt[c];
        int start = sh_cstart[c];
        const unsigned char* Mp = sh_gm[c] ? &g_cmat_ovf[b][sh_cmoff[c]] : &cmat[sh_cmoff[c]];
        u64 kept = 0;
        if (n > 0 && n <= 64) {
            u64 sup = 0;
            for (int r = 0; r < n; ++r) {
                if ((sup >> r) & 1ULL) continue;
                int gi = (int)sh_member[start + r];
                if (!((sh_validw[gi >> 5] >> (gi & 31)) & 1u)) continue;
                kept |= 1ULL << r;
                const unsigned char* row = Mp + r * n;
                for (int rr = r + 1; rr < n; ++rr)
                    if ((int)row[rr] > t) sup |= 1ULL << rr;
            }
        } else if (n > 64) {
            u64 sup[16];
            #pragma unroll
            for (int w2 = 0; w2 < 16; ++w2) sup[w2] = 0;
            for (int r = 0; r < n; ++r) {
                if ((sup[r >> 6] >> (r & 63)) & 1ULL) continue;
                int gi = (int)sh_member[start + r];
                if (!((sh_validw[gi >> 5] >> (gi & 31)) & 1u)) continue;
                atomicOr(&keepw2[t][gi >> 5], 1u << (gi & 31));
                const unsigned char* row = Mp + r * n;
                for (int rr = r + 1; rr < n; ++rr)
                    if ((int)row[rr] > t) sup[rr >> 6] |= 1ULL << (rr & 63);
            }
            kept = 0;
        }
        uB.mask[t][c] = kept;
    }
    __syncthreads();

    /* phase 2: ballot-assemble keep words in candidate (gi) order */
    {
        int c = (int)sh_cls[tid];
        int r = (int)sh_loc[tid];
        #pragma unroll
        for (int t = 0; t < NTH; ++t) {
            int bit = (r < 64) ? (int)((uB.mask[t][c] >> r) & 1ULL) : 0;
            unsigned bal = __ballot_sync(0xffffffffu, bit);
            if (lane == 0) keepw[t][wid] = bal | keepw2[t][wid];
        }
    }
    __syncthreads();

    if (tid < NTH) {
        int s = 0;
        #pragma unroll
        for (int w2 = 0; w2 < 32; ++w2) s += __popc(keepw[tid][w2]);
        cnt_t[tid] = s;
    }
    __syncthreads();

    if (tid == 0) {
        int tsel = NTH - 1;
        for (int q = 0; q < NTH; ++q)
            if (cnt_t[q] >= 6) { tsel = q; break; }
        int found = 0;
        for (int w2 = 0; w2 < 32 && found < 6; ++w2) {
            unsigned m = keepw[tsel][w2];
            while (m && found < 6) {
                int bpos = __ffs(m) - 1;
                m &= m - 1;
                selp[found++] = g_prop[b][w2 * 32 + bpos];
            }
        }
        if (found < 6) {
            for (int gi = 0; gi < KCAND && found < 6; ++gi)
                if (!((keepw[tsel][gi >> 5] >> (gi & 31)) & 1u))
                    selp[found++] = g_prop[b][gi];
        }
    }
    __syncthreads();

    /* fused feature gather: out[b][d][j] = feats[b][selp[j]][d] */
    int p0 = selp[0], p1 = selp[1], p2 = selp[2];
    int p3 = selp[3], p4 = selp[4], p5 = selp[5];
    const float* fb = feats + (size_t)b * NPROP * DFEAT;
    float* ob = out + (size_t)b * DFEAT * 6;
    for (int d = tid; d < DFEAT; d += 1024) {
        float* o = ob + d * 6;
        o[0] = fb[(size_t)p0 * DFEAT + d];
        o[1] = fb[(size_t)p1 * DFEAT + d];
        o[2] = fb[(size_t)p2 * DFEAT + d];
        o[3] = fb[(size_t)p3 * DFEAT + d];
        o[4] = fb[(size_t)p4 * DFEAT + d];
        o[5] = fb[(size_t)p5 * DFEAT + d];
    }
}

/* ---------------- launch -------------------------------------------------- */
extern "C" void kernel_launch(void* const* d_in, const int* in_sizes, int n_in,
                              void* d_out, int out_size)
{
    (void)in_sizes; (void)n_in; (void)out_size;
    const float* logits = (const float*)d_in[0];
    const float* boxes  = (const float*)d_in[1];
    const float* feats  = (const float*)d_in[2];
    const int*   hw     = (const int*)  d_in[3];
    float* out = (float*)d_out;

    k_front<<<NBLK1, 256>>>(logits);
    k_back<<<BATCH, 1024>>>(boxes, hw, feats, out);
}